// round 3
// baseline (speedup 1.0000x reference)
#include <cuda_runtime.h>
#include <cuda_bf16.h>

// VQLayer forward == identity copy of `inputs` (verified R1: rel_err 1.1e-8).
//   quantized = closest + stop_gradient(inputs - closest) == inputs (forward value).
//
// R1 post-mortem: 1-float4-per-thread copy was latency-bound (MLP_p1=1,
// DRAM 17.5%, 1.7 waves). R2: one-wave launch, 4 independent float4 loads
// per thread front-batched (MLP=4), streaming cache hints (no reuse).
// 512 blocks x 256 threads x 4 float4 = 524288 float4 = 2097152 floats exactly.

__global__ void vq_copy_mlp4_kernel(const float4* __restrict__ in,
                                    float4* __restrict__ out) {
    // Each block owns a contiguous 1024-float4 (16 KB) segment.
    int base = blockIdx.x * 1024 + threadIdx.x;
    // Front-batched independent loads: 4 LDG.128 in flight per thread.
    float4 a = __ldcs(in + base);
    float4 b = __ldcs(in + base + 256);
    float4 c = __ldcs(in + base + 512);
    float4 d = __ldcs(in + base + 768);
    __stcs(out + base,       a);
    __stcs(out + base + 256, b);
    __stcs(out + base + 512, c);
    __stcs(out + base + 768, d);
}

// Fallback for any size not divisible by 1024 float4s (not expected here).
__global__ void vq_copy_gs_kernel(const float4* __restrict__ in,
                                  float4* __restrict__ out, int n4) {
    int i = blockIdx.x * blockDim.x + threadIdx.x;
    for (; i < n4; i += gridDim.x * blockDim.x)
        out[i] = in[i];
}

extern "C" void kernel_launch(void* const* d_in, const int* in_sizes, int n_in,
                              void* d_out, int out_size) {
    const float4* in = (const float4*)d_in[0];
    float4* out = (float4*)d_out;

    int n4 = out_size / 4;  // 524288 expected
    if ((out_size % 4 == 0) && (n4 % 1024 == 0)) {
        int grid = n4 / 1024;  // 512 blocks -> exactly one wave on 148 SMs
        vq_copy_mlp4_kernel<<<grid, 256>>>(in, out);
    } else {
        int grid = (n4 + 255) / 256;
        vq_copy_gs_kernel<<<grid, 256>>>(in, out, n4);
    }
}